// round 3
// baseline (speedup 1.0000x reference)
#include <cuda_runtime.h>

// SNN MLP restructured:
//   k1: static_input = inp @ W1^T  (fp32 SGEMM, 16384x800x784)
//       + fused 32-step LIF recurrence -> spike counts s[b,j] (device scratch)
//   k2: out = (s @ W2^T) / 32
//
// Determinism: no atomics, fixed reduction orders.

#define BM 128
#define BN 64
#define BK 16
#define TM 8
#define TN 4
#define PADA 4
#define PADB 4
#define KDIM 784
#define NDIM 800
#define MDIM 16384
#define KTILES (KDIM / BK)   // 49

// Spike-count scratch (float counts 0..32, exactly representable)
__device__ float g_s[(size_t)MDIM * NDIM];

__global__ __launch_bounds__(256)
void snn_fc1_lif_kernel(const float* __restrict__ A,   // [16384, 784]
                        const float* __restrict__ W1)  // [800, 784]
{
    __shared__ float As[2][BK][BM + PADA];
    __shared__ float Bs[2][BK][BN + PADB];

    const int tid = threadIdx.x;
    const int tx  = tid & 15;   // 0..15 (N direction, TN=4 each)
    const int ty  = tid >> 4;   // 0..15 (M direction, TM=8 each)
    const int m0  = blockIdx.y * BM;
    const int n0  = blockIdx.x * BN;

    // Global-load assignment: A tile = 512 float4 (2/thread), B tile = 256 float4 (1/thread)
    const int arow0 = tid >> 2;                 // rows 0..63
    const int arow1 = (tid + 256) >> 2;         // rows 64..127
    const int ak4   = tid & 3;                  // float4 column within BK
    const int brow  = tid >> 2;                 // 0..63
    const int bk4   = tid & 3;

    const float* Arow0 = A + (size_t)(m0 + arow0) * KDIM;
    const float* Arow1 = A + (size_t)(m0 + arow1) * KDIM;
    const bool  bvalid = (n0 + brow) < NDIM;
    const float* Brow  = W1 + (size_t)(n0 + brow) * KDIM;

    float4 a0, a1, b0;

    // Prefetch tile 0
    a0 = *(const float4*)(Arow0 + ak4 * 4);
    a1 = *(const float4*)(Arow1 + ak4 * 4);
    b0 = bvalid ? *(const float4*)(Brow + bk4 * 4) : make_float4(0.f, 0.f, 0.f, 0.f);

#define STORE_TILE(B_)                                                          \
    do {                                                                        \
        As[B_][ak4 * 4 + 0][arow0] = a0.x;                                      \
        As[B_][ak4 * 4 + 1][arow0] = a0.y;                                      \
        As[B_][ak4 * 4 + 2][arow0] = a0.z;                                      \
        As[B_][ak4 * 4 + 3][arow0] = a0.w;                                      \
        As[B_][ak4 * 4 + 0][arow1] = a1.x;                                      \
        As[B_][ak4 * 4 + 1][arow1] = a1.y;                                      \
        As[B_][ak4 * 4 + 2][arow1] = a1.z;                                      \
        As[B_][ak4 * 4 + 3][arow1] = a1.w;                                      \
        Bs[B_][bk4 * 4 + 0][brow]  = b0.x;                                      \
        Bs[B_][bk4 * 4 + 1][brow]  = b0.y;                                      \
        Bs[B_][bk4 * 4 + 2][brow]  = b0.z;                                      \
        Bs[B_][bk4 * 4 + 3][brow]  = b0.w;                                      \
    } while (0)

    STORE_TILE(0);
    __syncthreads();

    float acc[TM][TN];
#pragma unroll
    for (int i = 0; i < TM; i++)
#pragma unroll
        for (int j = 0; j < TN; j++) acc[i][j] = 0.f;

    int buf = 0;
    for (int t = 0; t < KTILES; ++t) {
        if (t + 1 < KTILES) {
            const int ko = (t + 1) * BK;
            a0 = *(const float4*)(Arow0 + ko + ak4 * 4);
            a1 = *(const float4*)(Arow1 + ko + ak4 * 4);
            b0 = bvalid ? *(const float4*)(Brow + ko + bk4 * 4)
                        : make_float4(0.f, 0.f, 0.f, 0.f);
        }
#pragma unroll
        for (int kk = 0; kk < BK; ++kk) {
            float4 ra0 = *(const float4*)&As[buf][kk][ty * TM];
            float4 ra1 = *(const float4*)&As[buf][kk][ty * TM + 4];
            float4 rb  = *(const float4*)&Bs[buf][kk][tx * TN];
            float am[TM] = {ra0.x, ra0.y, ra0.z, ra0.w, ra1.x, ra1.y, ra1.z, ra1.w};
            float bn[TN] = {rb.x, rb.y, rb.z, rb.w};
#pragma unroll
            for (int i = 0; i < TM; i++)
#pragma unroll
                for (int j = 0; j < TN; j++)
                    acc[i][j] = fmaf(am[i], bn[j], acc[i][j]);
        }
        if (t + 1 < KTILES) {
            STORE_TILE(buf ^ 1);
            __syncthreads();
            buf ^= 1;
        }
    }
#undef STORE_TILE

    // ---- Fused LIF recurrence: spike counts from static_input ----
    // mem = 0.95*mem + 0.05*c ; spike iff mem > 1 ; on spike mem -= 1
    // Explicit round-to-nearest intrinsics: no FMA contraction (match reference).
    const int nb = n0 + tx * TN;
    if (nb < NDIM) {
#pragma unroll
        for (int i = 0; i < TM; i++) {
            float mem[TN] = {0.f, 0.f, 0.f, 0.f};
            float cnt[TN] = {0.f, 0.f, 0.f, 0.f};
            for (int s = 0; s < 32; ++s) {
#pragma unroll
                for (int j = 0; j < TN; j++) {
                    mem[j] = __fadd_rn(__fmul_rn(0.95f, mem[j]),
                                       __fmul_rn(0.05f, acc[i][j]));
                    if (mem[j] > 1.0f) {
                        cnt[j] += 1.0f;
                        mem[j] -= 1.0f;
                    }
                }
            }
            const int m = m0 + ty * TM + i;
            *(float4*)&g_s[(size_t)m * NDIM + nb] =
                make_float4(cnt[0], cnt[1], cnt[2], cnt[3]);
        }
    }
}

// out[b,k] = (sum_j s[b,j] * W2[k,j]) / 32 ; one warp per row b.
__global__ __launch_bounds__(256)
void snn_fc2_kernel(const float* __restrict__ W2,   // [10, 800]
                    float* __restrict__ out)        // [16384, 10]
{
    __shared__ float W2s[NDIM * 10];   // W2s[j*10 + k] = W2[k*800 + j]
    const int tid = threadIdx.x;
    for (int i = tid; i < NDIM * 10; i += 256) {
        int j = i / 10;
        int k = i - j * 10;
        W2s[i] = W2[k * NDIM + j];
    }
    __syncthreads();

    const int warp = tid >> 5;
    const int lane = tid & 31;
    const int row  = blockIdx.x * 8 + warp;

    float acc[10];
#pragma unroll
    for (int k = 0; k < 10; k++) acc[k] = 0.f;

    const float* __restrict__ srow = g_s + (size_t)row * NDIM;
    for (int j = lane; j < NDIM; j += 32) {
        float sv = srow[j];
#pragma unroll
        for (int k = 0; k < 10; k++)
            acc[k] = fmaf(sv, W2s[j * 10 + k], acc[k]);
    }
#pragma unroll
    for (int k = 0; k < 10; k++) {
#pragma unroll
        for (int off = 16; off; off >>= 1)
            acc[k] += __shfl_xor_sync(0xffffffffu, acc[k], off);
    }
    if (lane < 10)
        out[row * 10 + lane] = acc[lane] * 0.03125f;   // exact /32
}

extern "C" void kernel_launch(void* const* d_in, const int* in_sizes, int n_in,
                              void* d_out, int out_size)
{
    const float* inp = (const float*)d_in[0];   // [16384,1,28,28] -> [16384,784]
    const float* W1  = (const float*)d_in[1];   // [800,784]
    const float* W2  = (const float*)d_in[2];   // [10,800]
    float* out = (float*)d_out;                 // [16384,10]

    dim3 grid1((NDIM + BN - 1) / BN, MDIM / BM);   // (13, 128)
    snn_fc1_lif_kernel<<<grid1, 256>>>(inp, W1);
    snn_fc2_kernel<<<MDIM / 8, 256>>>(W2, out);
}